// round 17
// baseline (speedup 1.0000x reference)
#include <cuda_runtime.h>
#include <cuda_bf16.h>
#include <cstdint>

#define NROWS 65536
#define DDIM  512
#define KCL   1024
#define MT    128
#define KC    32
#define NCH   16                       // k-chunks per K pass (DDIM/KC)
#define ASTRIDE 520                    // bf16 per A row (pad) -> 1040B
#define BROWB 80                       // bytes per B slab row (32 bf16 + 16B pad)
#define BSTG  (32 * BROWB)             // 2560 B per slab stage

// smem byte offsets
#define AS_OFF 0
#define BS_OFF (MT * ASTRIDE * 2)            // 133120
#define CS_OFF (BS_OFF + 16 * 2 * BSTG)      // 215040
#define XS_OFF (CS_OFF + KCL * 4)            // 219136
#define RS_OFF (XS_OFF + MT * 4)             // 219648
#define SMEM_TOTAL (RS_OFF + MT * 4)         // 220160

__device__ __align__(1024) __nv_bfloat16 g_cb[KCL * DDIM];  // clusters bf16
__device__ float g_csq[KCL];

static __device__ __forceinline__ uint32_t smaddr(const void* p) {
    return (uint32_t)__cvta_generic_to_shared(p);
}
static __device__ __forceinline__ void ldmatrix_x4(uint32_t r[4], uint32_t addr) {
    asm volatile("ldmatrix.sync.aligned.m8n8.x4.shared.b16 {%0,%1,%2,%3}, [%4];"
                 : "=r"(r[0]), "=r"(r[1]), "=r"(r[2]), "=r"(r[3]) : "r"(addr));
}
static __device__ __forceinline__ void mma_bf16(float c[4], const uint32_t a[4],
                                                uint32_t b0, uint32_t b1) {
    asm volatile(
        "mma.sync.aligned.m16n8k16.row.col.f32.bf16.bf16.f32 "
        "{%0,%1,%2,%3}, {%4,%5,%6,%7}, {%8,%9}, {%0,%1,%2,%3};"
        : "+f"(c[0]), "+f"(c[1]), "+f"(c[2]), "+f"(c[3])
        : "r"(a[0]), "r"(a[1]), "r"(a[2]), "r"(a[3]), "r"(b0), "r"(b1));
}

// ---------------- prep: clusters fp32 -> bf16, and ||c||^2 ----------------
__global__ void prep_clusters(const float* __restrict__ cl) {
    int row = blockIdx.x, t = threadIdx.x;
    float v = cl[row * DDIM + t];
    g_cb[row * DDIM + t] = __float2bfloat16_rn(v);
    float s = v * v;
    #pragma unroll
    for (int o = 16; o > 0; o >>= 1) s += __shfl_down_sync(0xffffffffu, s, o);
    __shared__ float ws[16];
    if ((t & 31) == 0) ws[t >> 5] = s;
    __syncthreads();
    if (t < 16) {
        float x2 = ws[t];
        #pragma unroll
        for (int o = 8; o > 0; o >>= 1) x2 += __shfl_down_sync(0xffffu, x2, o);
        if (t == 0) g_csq[row] = x2;
    }
}

// ------- main fused HMMA kernel: 512 thr, 16 fully independent warp pipelines -------
__global__ void __launch_bounds__(512, 1)
cluster_main(const float* __restrict__ x, float* __restrict__ out) {
    extern __shared__ __align__(1024) char sm[];
    const uint32_t sb = smaddr(sm);
    __nv_bfloat16* As = (__nv_bfloat16*)(sm + AS_OFF);
    float* cs = (float*)(sm + CS_OFF);
    float* xs = (float*)(sm + XS_OFF);
    float* rs = (float*)(sm + RS_OFF);

    const int tid  = threadIdx.x;
    const int lane = tid & 31;
    const int warp = tid >> 5;
    const int colb = warp * 64;            // warp's private 64 N-columns
    const int m0   = blockIdx.x * MT;

    if (tid < MT) rs[tid] = 0.f;
    for (int i = tid; i < KCL; i += 512) cs[i] = g_csq[i];

    // A tile: 128 x 512 fp32 -> bf16 smem; per-row ||x||^2 (whole CTA)
    {
        const int row = tid >> 2, q = tid & 3;
        const float4* src = (const float4*)(x + (size_t)(m0 + row) * DDIM + q * 128);
        float s = 0.f;
        #pragma unroll 4
        for (int i = 0; i < 32; i++) {
            float4 v = src[i];
            s += v.x * v.x + v.y * v.y + v.z * v.z + v.w * v.w;
            __nv_bfloat162 p0 = __floats2bfloat162_rn(v.x, v.y);
            __nv_bfloat162 p1 = __floats2bfloat162_rn(v.z, v.w);
            uint2 pk; pk.x = *(uint32_t*)&p0; pk.y = *(uint32_t*)&p1;
            *(uint2*)&As[row * ASTRIDE + q * 128 + i * 4] = pk;
        }
        s += __shfl_xor_sync(0xffffffffu, s, 1);
        s += __shfl_xor_sync(0xffffffffu, s, 2);
        if ((lane & 3) == 0) xs[row] = s;
    }
    __syncthreads();   // A + xs + rs + cs ready; NO block barriers until the end

    // warp-private stage bases (2 slots)
    const uint32_t stg0 = sb + BS_OFF + (uint32_t)(warp * 2) * BSTG;

    // invariant lane address parts
    const uint32_t a_lrow = (uint32_t)((lane & 7) + ((lane >> 3) & 1) * 8);
    const uint32_t a_lcol = (uint32_t)(lane >> 4) * 16;
    // B ldmatrix: within 16-row group, row (lane>>4)*8 + (lane&7), col half ((lane>>3)&1)*16B
    const uint32_t b_lrow = (uint32_t)((lane >> 4) * 8 + (lane & 7)) * BROWB;
    const uint32_t b_lcol = (uint32_t)((lane >> 3) & 1) * 16;

    // copy one warp-private B slab (32 N-rows x 32 K-cols bf16): 128 x 16B
    auto cp_slab = [&](int nb, int c) {
        const __nv_bfloat16* src0 = g_cb + (size_t)nb * DDIM + c * KC;
        const uint32_t dbase = stg0 + (uint32_t)(c & 1) * BSTG;
        #pragma unroll
        for (int j = 0; j < 4; j++) {
            int g = j * 32 + lane;          // [0,128)
            int row = g >> 2, cc = g & 3;
            const __nv_bfloat16* gp = src0 + (size_t)row * DDIM + cc * 8;
            asm volatile("cp.async.cg.shared.global [%0], [%1], 16;"
                         :: "r"(dbase + row * BROWB + cc * 16), "l"(gp));
        }
        asm volatile("cp.async.commit_group;");
    };

    float acc[4][4][4];

    #pragma unroll 1
    for (int nh = 0; nh < 2; nh++) {
        const int nb = colb + nh * 32;     // slab's 32 N-columns
        #pragma unroll 1
        for (int mh = 0; mh < 2; mh++) {
            const int mb = mh * 64;        // slab's 64 M-rows
            uint32_t a_base[4];
            #pragma unroll
            for (int mi = 0; mi < 4; mi++)
                a_base[mi] = sb + AS_OFF +
                    (uint32_t)((mb + mi * 16 + a_lrow) * ASTRIDE) * 2 + a_lcol;

            #pragma unroll
            for (int mi = 0; mi < 4; mi++)
                #pragma unroll
                for (int ni = 0; ni < 4; ni++)
                    #pragma unroll
                    for (int r = 0; r < 4; r++) acc[mi][ni][r] = 0.f;

            cp_slab(nb, 0);
            #pragma unroll 1
            for (int c = 0; c < NCH; c++) {
                if (c + 1 < NCH) {
                    cp_slab(nb, c + 1);
                    asm volatile("cp.async.wait_group 1;");
                } else {
                    asm volatile("cp.async.wait_group 0;");
                }
                __syncwarp();              // all lanes' copies of chunk c landed

                const uint32_t bst = stg0 + (uint32_t)(c & 1) * BSTG + b_lrow + b_lcol;
                #pragma unroll
                for (int ks = 0; ks < 2; ks++) {
                    const int kk = c * KC + ks * 16;
                    uint32_t a[4][4], b[2][4];
                    #pragma unroll
                    for (int mi = 0; mi < 4; mi++)
                        ldmatrix_x4(a[mi], a_base[mi] + kk * 2);
                    ldmatrix_x4(b[0], bst + ks * 32);                   // slab rows 0-15
                    ldmatrix_x4(b[1], bst + 16 * BROWB + ks * 32);      // slab rows 16-31
                    #pragma unroll
                    for (int mi = 0; mi < 4; mi++)
                        #pragma unroll
                        for (int ni = 0; ni < 4; ni++)
                            mma_bf16(acc[mi][ni], a[mi],
                                     b[ni >> 1][(ni & 1) * 2],
                                     b[ni >> 1][(ni & 1) * 2 + 1]);
                }
            }

            // epilogue for this slab: q = 1/(1+dist2), store, row-sums
            #pragma unroll
            for (int mi = 0; mi < 4; mi++) {
                const int rlo = mb + mi * 16 + (lane >> 2);
                const int rhi = rlo + 8;
                const float xlo = xs[rlo], xhi = xs[rhi];
                float rs0 = 0.f, rs1 = 0.f;
                #pragma unroll
                for (int ni = 0; ni < 4; ni++) {
                    const int c = nb + ni * 8 + (lane & 3) * 2;
                    const float2 cc = *(const float2*)&cs[c];
                    float q00 = __fdividef(1.f, 1.f + fmaxf(xlo + cc.x - 2.f * acc[mi][ni][0], 0.f));
                    float q01 = __fdividef(1.f, 1.f + fmaxf(xlo + cc.y - 2.f * acc[mi][ni][1], 0.f));
                    float q10 = __fdividef(1.f, 1.f + fmaxf(xhi + cc.x - 2.f * acc[mi][ni][2], 0.f));
                    float q11 = __fdividef(1.f, 1.f + fmaxf(xhi + cc.y - 2.f * acc[mi][ni][3], 0.f));
                    *(float2*)&out[(size_t)(m0 + rlo) * KCL + c] = make_float2(q00, q01);
                    *(float2*)&out[(size_t)(m0 + rhi) * KCL + c] = make_float2(q10, q11);
                    rs0 += q00 + q01;
                    rs1 += q10 + q11;
                }
                rs0 += __shfl_xor_sync(0xffffffffu, rs0, 1);
                rs0 += __shfl_xor_sync(0xffffffffu, rs0, 2);
                rs1 += __shfl_xor_sync(0xffffffffu, rs1, 1);
                rs1 += __shfl_xor_sync(0xffffffffu, rs1, 2);
                if ((lane & 3) == 0) {
                    atomicAdd(&rs[rlo], rs0);
                    atomicAdd(&rs[rhi], rs1);
                }
            }
        }
    }
    __syncthreads();   // all stores + row-sum atomics done

    // normalize pass: CTA's own 512KB out region (L2-hot)
    {
        const int row = tid >> 2, q = tid & 3;
        const float inv = __fdividef(1.f, rs[row]);
        float4* p = (float4*)(out + (size_t)(m0 + row) * KCL + q * 256);
        #pragma unroll 4
        for (int i = 0; i < 64; i++) {
            float4 v = p[i];
            v.x *= inv; v.y *= inv; v.z *= inv; v.w *= inv;
            p[i] = v;
        }
    }
}

extern "C" void kernel_launch(void* const* d_in, const int* in_sizes, int n_in,
                              void* d_out, int out_size) {
    const float* x        = (const float*)d_in[0];
    const float* clusters = (const float*)d_in[1];
    float* out = (float*)d_out;

    cudaFuncSetAttribute(cluster_main,
                         cudaFuncAttributeMaxDynamicSharedMemorySize, SMEM_TOTAL);

    prep_clusters<<<KCL, DDIM>>>(clusters);
    cluster_main<<<NROWS / MT, 512, SMEM_TOTAL>>>(x, out);
}